// round 6
// baseline (speedup 1.0000x reference)
#include <cuda_runtime.h>
#include <cuda_bf16.h>

// CustomEmbedding: out[tok,:] = (x[tok] < 1000) ? sin((x/1000)*(d+1)) : weight[x,:]
// x: (32768,) int32 | weight: (50000,512) f32 | out: (32768,512) f32
//
// R4 finding: MLP=8/thread cost occupancy (72%->46%), net wash. In-flight
// bytes = occ * MLP; need both. Shape: pipelined grid-stride, 1 token per
// warp per iteration (4 iterations/warp), with the NEXT token's id prefetched
// (unconditionally, clamped address) at the top of each iteration -> dependent
// id->row chain hidden across iterations at near-zero register cost. MLP=4
// row loads, branch-free gather, sinusoid patch for ids<1000, __stcs
// streaming stores (output write-once; keep weight table L2-resident).

#define VEC 128            // float4 per 512-float row
#define NUM_NUM 1000
#define BLOCKS 1024
#define THREADS 256        // 8 warps/block -> 8192 warps -> 4 tokens/warp

__device__ __forceinline__ void sin_row(int id, int lane, float4* v)
{
    float s = (float)id * 1e-3f;
    #pragma unroll
    for (int j = 0; j < 4; j++) {
        int d0 = (lane + j * 32) * 4;
        v[j].x = sinf(s * (float)(d0 + 1));
        v[j].y = sinf(s * (float)(d0 + 2));
        v[j].z = sinf(s * (float)(d0 + 3));
        v[j].w = sinf(s * (float)(d0 + 4));
    }
}

__global__ void __launch_bounds__(THREADS, 6) custom_embedding_kernel(
    const int* __restrict__ x,
    const float4* __restrict__ weight,   // (VOCAB, 128) float4
    float4* __restrict__ out,            // (NTOK, 128) float4
    int ntok, int nwarps)
{
    int warp_g = (blockIdx.x * THREADS + threadIdx.x) >> 5;
    int lane   = threadIdx.x & 31;

    int tok = warp_g;
    if (tok >= ntok) return;
    int id = __ldg(&x[tok]);             // first id (exposed once per warp)

    while (true) {
        // unconditional prefetch of next iteration's id (clamped address)
        int tok_next = tok + nwarps;
        bool has_next = (tok_next < ntok);
        int tok_pf = has_next ? tok_next : (ntok - 1);
        int id_next = __ldg(&x[tok_pf]);

        // branch-free row gather, 4 independent 16B loads in flight
        const float4* __restrict__ s = weight + (size_t)id * VEC;
        float4 v[4];
        v[0] = __ldg(&s[lane]);
        v[1] = __ldg(&s[lane + 32]);
        v[2] = __ldg(&s[lane + 64]);
        v[3] = __ldg(&s[lane + 96]);

        // numeric tokens (~3%): overwrite with sinusoidal row
        if (id < NUM_NUM) sin_row(id, lane, v);

        // streaming stores: evict-first, keep weight table L2-resident
        float4* __restrict__ d = out + (size_t)tok * VEC;
        __stcs(&d[lane],      v[0]);
        __stcs(&d[lane + 32], v[1]);
        __stcs(&d[lane + 64], v[2]);
        __stcs(&d[lane + 96], v[3]);

        if (!has_next) break;
        tok = tok_next;
        id  = id_next;
    }
}

extern "C" void kernel_launch(void* const* d_in, const int* in_sizes, int n_in,
                              void* d_out, int out_size)
{
    // metadata order: x (int32), weight (f32), num_value (int32), is_num (bool)
    const int*    x      = (const int*)d_in[0];
    const float4* weight = (const float4*)d_in[1];
    float4*       out    = (float4*)d_out;

    int ntok   = in_sizes[0];                // 32768
    int nwarps = BLOCKS * (THREADS / 32);    // 8192 -> 4 tokens per warp
    custom_embedding_kernel<<<BLOCKS, THREADS>>>(x, weight, out, ntok, nwarps);
}